// round 10
// baseline (speedup 1.0000x reference)
#include <cuda_runtime.h>
#include <cstdint>
#include <math.h>

#define BB 128      // batch
#define SS 4096     // seq
#define DD 256      // value/query dim
#define UU 128      // units
#define SPLITS 8
#define CHUNK (SS/SPLITS)     // 512
#define TILE 64
#define NTILES (CHUNK/TILE)   // 8
#define VPAD 260              // values smem row stride (conflict-free)
#define PPAD 132              // partial-exchange row stride (conflict-free)

// -------- scratch (no allocations allowed) --------
__device__ float g_qb[BB*UU];             // q@W1 + b1 + b2
__device__ float g_scores[BB*SS];         // exp(score), unnormalized
__device__ float g_ps[BB*SPLITS];         // per-chunk expsum
__device__ float g_pctx[BB*SPLITS*DD];    // per-chunk unnormalized context
__device__ float g_inv[BB];               // 1/sum

__device__ __forceinline__ uint32_t tf32_rna(float x) {
    uint32_t r;
    asm("cvt.rna.tf32.f32 %0, %1;" : "=r"(r) : "f"(x));
    return r;
}

#define MMA4(ACC, AF, B0, B1)                                                  \
    asm volatile(                                                              \
        "mma.sync.aligned.m16n8k8.row.col.f32.tf32.tf32.f32 "                  \
        "{%0,%1,%2,%3}, {%4,%5,%6,%7}, {%8,%9}, {%0,%1,%2,%3};"                \
        : "+f"((ACC)[0]), "+f"((ACC)[1]), "+f"((ACC)[2]), "+f"((ACC)[3])       \
        : "r"((AF)[0]), "r"((AF)[1]), "r"((AF)[2]), "r"((AF)[3]),              \
          "r"(B0), "r"(B1))

// ---------------- kernel 1: q_proj = query @ W1 + b1 + b2 ----------------
__global__ void qproj_kernel(const float* __restrict__ query,
                             const float* __restrict__ W1,
                             const float* __restrict__ b1,
                             const float* __restrict__ b2) {
    __shared__ float q[DD];
    int b = blockIdx.x, u = threadIdx.x;      // 128 threads
    q[u]       = query[b*DD + u];
    q[u + 128] = query[b*DD + u + 128];
    __syncthreads();
    float acc = b1[u] + b2[u];
    #pragma unroll 8
    for (int d = 0; d < DD; d++) acc += q[d] * W1[d*UU + u];
    g_qb[b*UU + u] = acc;
}

// ---------------- kernel 2: main fused pass ----------------
// grid (SPLITS, BB), 512 threads = 16 warps.
// Warp w: K-half = w>>3, units [16*(w&7), +16). A fragments (64 regs) in
// registers. Partial v_proj sums exchanged via SMEM; epilogue (tanh,score)
// alternates between K-half groups per chunk-pair so it overlaps the other
// group's MMA. Scores tanh-bounded -> exp without max subtraction.
extern __shared__ float smem[];

__global__ void __launch_bounds__(512, 1)
attn_main(const float* __restrict__ values,
          const float* __restrict__ W2,
          const float* __restrict__ Wv) {
    float* valsb = smem;                        // 2 x [TILE][VPAD]
    float* pex   = valsb + 2*TILE*VPAD;         // 2 x [16][PPAD] partial exch
    float* spart = pex + 2*16*PPAD;             // [8 warps][64 cols]
    float* sp    = spart + 8*64;                // [64] exp(score) per row
    float* sred  = sp + 64;                     // [2]
    float* ctxb  = pex;                         // reused at end (256 floats)

    const int b = blockIdx.y, split = blockIdx.x;
    const int s0 = split * CHUNK;
    const int tid = threadIdx.x;
    const int lane = tid & 31, wid = tid >> 5;
    const int khalf = wid >> 3, uw = wid & 7;
    const int u0 = uw * 16;
    const int g = lane >> 2, t = lane & 3;
    const int chalf = tid >> 8, ccol = tid & 255;

    // async tile loader: 64 rows x 256 floats, 8 x 16B per thread
    auto load_tile = [&](int tile, int bufsel) {
        const float* src = values + (((size_t)b*SS + s0 + tile*TILE) * DD);
        float* dst = valsb + bufsel*TILE*VPAD;
        #pragma unroll
        for (int p = 0; p < 8; p++) {
            int e = p*2048 + tid*4;
            int row = e >> 8, col = e & 255;
            uint32_t da = (uint32_t)__cvta_generic_to_shared(dst + row*VPAD + col);
            asm volatile("cp.async.cg.shared.global [%0], [%1], 16;"
                         :: "r"(da), "l"(src + row*DD + col));
        }
        asm volatile("cp.async.commit_group;");
    };
    load_tile(0, 0);

    // ---- A fragments: W2^T rows [u0,u0+16), K-half [128*khalf, +128) ----
    uint32_t Af[16][4];
    #pragma unroll
    for (int kk = 0; kk < 16; kk++) {
        const float* w = W2 + (khalf*128 + kk*8 + t) * UU;
        Af[kk][0] = tf32_rna(w[u0 + g]);
        Af[kk][1] = tf32_rna(w[u0 + 8 + g]);
        Af[kk][2] = tf32_rna(w[4*UU + u0 + g]);
        Af[kk][3] = tf32_rna(w[4*UU + u0 + 8 + g]);
    }
    const float qbg = g_qb[b*UU + u0 + g], qb8 = g_qb[b*UU + u0 + 8 + g];
    const float wvg = Wv[u0 + g],          wv8 = Wv[u0 + 8 + g];

    float cacc = 0.f;     // context partial for (row-half chalf, col ccol)
    float sacc = 0.f;     // exp-sum partial (tid < 64)

    for (int tile = 0; tile < NTILES; ++tile) {
        const int buf = tile & 1;
        asm volatile("cp.async.wait_group 0;");
        __syncthreads();
        if (tile + 1 < NTILES) load_tile(tile + 1, buf ^ 1);
        const float* va = valsb + buf*TILE*VPAD;

        // ---- 4 chunk-pairs of 16 seq rows ----
        #pragma unroll 1
        for (int c = 0; c < 4; c++) {
            const int n0 = c * 16;
            float accA[4] = {0.f,0.f,0.f,0.f};   // seq rows n0..n0+7
            float accB[4] = {0.f,0.f,0.f,0.f};   // seq rows n0+8..n0+15
            const float* brA = va + (n0 + g)*VPAD + khalf*128 + t;
            const float* brB = brA + 8*VPAD;
            #pragma unroll
            for (int kk = 0; kk < 16; kk++) {
                uint32_t bA0 = tf32_rna(brA[kk*8]);
                uint32_t bA1 = tf32_rna(brA[kk*8 + 4]);
                uint32_t bB0 = tf32_rna(brB[kk*8]);
                uint32_t bB1 = tf32_rna(brB[kk*8 + 4]);
                MMA4(accA, Af[kk], bA0, bA1);
                MMA4(accB, Af[kk], bB0, bB1);
            }

            // ---- exchange K-half partials; alternate writer group ----
            float* px = pex + (c & 1)*16*PPAD;
            const bool writer = (khalf == (c & 1));
            if (writer) {
                #pragma unroll
                for (int j = 0; j < 4; j++) {
                    int nn = 2*t + (j & 1), uu2 = u0 + (j >> 1)*8 + g;
                    px[nn*PPAD + uu2]       = accA[j];
                    px[(8 + nn)*PPAD + uu2] = accB[j];
                }
            }
            __syncthreads();
            if (!writer) {
                #pragma unroll
                for (int ch = 0; ch < 2; ch++) {
                    const float* ac = ch ? accB : accA;
                    const float* pr = px + ch*8*PPAD;
                    float a0 = ac[0] + pr[(2*t    )*PPAD + u0 + g];
                    float a1 = ac[1] + pr[(2*t + 1)*PPAD + u0 + g];
                    float a2 = ac[2] + pr[(2*t    )*PPAD + u0 + 8 + g];
                    float a3 = ac[3] + pr[(2*t + 1)*PPAD + u0 + 8 + g];
                    float e0 = tanhf(a0 + qbg) * wvg;
                    float e1 = tanhf(a1 + qbg) * wvg;
                    float e2 = tanhf(a2 + qb8) * wv8;
                    float e3 = tanhf(a3 + qb8) * wv8;
                    float sc0 = e0 + e2, sc1 = e1 + e3;
                    #pragma unroll
                    for (int o = 4; o <= 16; o <<= 1) {
                        sc0 += __shfl_xor_sync(0xffffffffu, sc0, o);
                        sc1 += __shfl_xor_sync(0xffffffffu, sc1, o);
                    }
                    if (lane < 4) {
                        spart[uw*64 + n0 + 8*ch + 2*lane    ] = sc0;
                        spart[uw*64 + n0 + 8*ch + 2*lane + 1] = sc1;
                    }
                }
            }
        }
        __syncthreads();

        // ---- cross-warp score reduce + exp (tanh-bounded, no max) ----
        if (tid < 64) {
            float sc = 0.f;
            #pragma unroll
            for (int w = 0; w < 8; w++) sc += spart[w*64 + tid];
            float p = __expf(sc);
            sp[tid] = p;
            sacc += p;
            g_scores[(size_t)b*SS + s0 + tile*TILE + tid] = p;
        }
        __syncthreads();

        // ---- context accumulate: each thread-half does 32 rows ----
        {
            const float* var = va + chalf*32*VPAD;
            const float* spr = sp + chalf*32;
            float csum = cacc;
            #pragma unroll 8
            for (int r = 0; r < 32; ++r)
                csum += spr[r] * var[r*VPAD + ccol];
            cacc = csum;
        }
    }

    // ---- finalize: exp-sum (warps 0,1 hold it) ----
    if (tid < 64) {
        float s = sacc;
        #pragma unroll
        for (int o = 16; o >= 1; o >>= 1) s += __shfl_xor_sync(0xffffffffu, s, o);
        if (lane == 0) sred[wid] = s;
    }
    __syncthreads();
    const int pi = b*SPLITS + split;
    if (tid == 0) g_ps[pi] = sred[0] + sred[1];

    // ---- combine context halves (ctxb aliases pex; free now) ----
    if (chalf == 1) ctxb[ccol] = cacc;
    __syncthreads();
    if (chalf == 0) g_pctx[pi*DD + ccol] = cacc + ctxb[ccol];
}

// ---------------- kernel 3: merge split partials -> context ----------------
__global__ void merge_kernel(float* __restrict__ out_ctx) {
    int b = blockIdx.x, tid = threadIdx.x;    // 256 threads
    __shared__ float sinv;
    if (tid == 0) {
        float s = 0.f;
        #pragma unroll
        for (int i = 0; i < SPLITS; i++) s += g_ps[b*SPLITS + i];
        float inv = 1.f / s;
        sinv = inv;
        g_inv[b] = inv;
    }
    __syncthreads();
    float c = 0.f;
    #pragma unroll
    for (int i = 0; i < SPLITS; i++) c += g_pctx[(b*SPLITS + i)*DD + tid];
    out_ctx[b*DD + tid] = c * sinv;
}

// ---------------- kernel 4: normalized attention weights ----------------
__global__ void weights_kernel(float* __restrict__ out_w) {
    int i = blockIdx.x * blockDim.x + threadIdx.x;  // B*S total
    int b = i >> 12;
    out_w[i] = g_scores[i] * g_inv[b];
}

extern "C" void kernel_launch(void* const* d_in, const int* in_sizes, int n_in,
                              void* d_out, int out_size) {
    const float* query  = (const float*)d_in[0];
    const float* values = (const float*)d_in[1];
    const float* W1     = (const float*)d_in[2];
    const float* b1     = (const float*)d_in[3];
    const float* W2     = (const float*)d_in[4];
    const float* b2     = (const float*)d_in[5];
    const float* Wv     = (const float*)d_in[6];
    // d_in[7] = bv: constant over seq -> cancels in softmax.
    float* out = (float*)d_out;

    qproj_kernel<<<BB, UU>>>(query, W1, b1, b2);

    size_t smem_bytes = (size_t)(2*TILE*VPAD + 2*16*PPAD + 8*64 + 64 + 8) * sizeof(float);
    cudaFuncSetAttribute(attn_main, cudaFuncAttributeMaxDynamicSharedMemorySize, (int)smem_bytes);
    attn_main<<<dim3(SPLITS, BB), 512, smem_bytes>>>(values, W2, Wv);

    merge_kernel<<<BB, DD>>>(out);                       // context -> out[0 : 32768)
    weights_kernel<<<(BB*SS)/256, 256>>>(out + BB*DD);   // weights -> out[32768 : )
}

// round 14
// speedup vs baseline: 1.1220x; 1.1220x over previous
#include <cuda_runtime.h>
#include <cstdint>
#include <math.h>

#define BB 128      // batch
#define SS 4096     // seq
#define DD 256      // value/query dim
#define UU 128      // units
#define SPLITS 8
#define CHUNK (SS/SPLITS)     // 512
#define TILE 64
#define NTILES (CHUNK/TILE)   // 8
#define VPAD 260              // values smem row stride (conflict-free)

// -------- scratch (no allocations allowed) --------
__device__ float g_qb[BB*UU];             // q@W1 + b1 + b2
__device__ float g_scores[BB*SS];         // exp(score), unnormalized
__device__ float g_ps[BB*SPLITS];         // per-chunk expsum
__device__ float g_pctx[BB*SPLITS*DD];    // per-chunk unnormalized context
__device__ float g_inv[BB];               // 1/sum

__device__ __forceinline__ uint32_t tf32_rna(float x) {
    uint32_t r;
    asm("cvt.rna.tf32.f32 %0, %1;" : "=r"(r) : "f"(x));
    return r;
}
__device__ __forceinline__ float fast_tanh(float x) {
    float r;
    asm("tanh.approx.f32 %0, %1;" : "=f"(r) : "f"(x));
    return r;
}

#define MMA4(A0,A1,A2,A3, AF, B0, B1)                                          \
    asm volatile(                                                              \
        "mma.sync.aligned.m16n8k8.row.col.f32.tf32.tf32.f32 "                  \
        "{%0,%1,%2,%3}, {%4,%5,%6,%7}, {%8,%9}, {%0,%1,%2,%3};"                \
        : "+f"(A0), "+f"(A1), "+f"(A2), "+f"(A3)                               \
        : "r"((AF)[0]), "r"((AF)[1]), "r"((AF)[2]), "r"((AF)[3]),              \
          "r"(B0), "r"(B1))

// ---------------- kernel 1: q_proj = query @ W1 + b1 + b2 ----------------
__global__ void qproj_kernel(const float* __restrict__ query,
                             const float* __restrict__ W1,
                             const float* __restrict__ b1,
                             const float* __restrict__ b2) {
    __shared__ float q[DD];
    int b = blockIdx.x, u = threadIdx.x;      // 128 threads
    q[u]       = query[b*DD + u];
    q[u + 128] = query[b*DD + u + 128];
    __syncthreads();
    float acc = b1[u] + b2[u];
    #pragma unroll 8
    for (int d = 0; d < DD; d++) acc += q[d] * W1[d*UU + u];
    g_qb[b*UU + u] = acc;
}

// ---------------- kernel 2: main fused pass ----------------
// grid (SPLITS, BB), 256 threads (R8 structure). A (W2^T) fully in registers;
// 4 independent MMA chains per warp. tanh via MUFU; score phase spread over
// all 256 threads (4 threads per seq column).
extern __shared__ float smem[];

__global__ void __launch_bounds__(256, 1)
attn_main(const float* __restrict__ values,
          const float* __restrict__ W2,
          const float* __restrict__ Wv) {
    float* valsb = smem;                        // 2 x [TILE][VPAD]
    float* spart = valsb + 2*TILE*VPAD;         // [8 warps][64 cols]
    float* sp    = spart + 8*64;                // [64] exp(score) per row
    float* sred  = sp + 64;                     // [8]

    const int b = blockIdx.y, split = blockIdx.x;
    const int s0 = split * CHUNK;
    const int tid = threadIdx.x;
    const int lane = tid & 31, wid = tid >> 5;
    const int g = lane >> 2, t = lane & 3;
    const int u0 = wid * 16;                    // each warp owns 16 units
    const int scol = tid >> 2, sj = tid & 3;    // score phase: 4 threads/col

    // async tile loader: 64 rows x 256 floats, 16 x 16B per thread
    auto load_tile = [&](int tile, int bufsel) {
        const float* src = values + (((size_t)b*SS + s0 + tile*TILE) * DD);
        float* dst = valsb + bufsel*TILE*VPAD;
        #pragma unroll
        for (int p = 0; p < 16; p++) {
            int e = p*1024 + tid*4;
            int row = e >> 8, col = e & 255;
            uint32_t da = (uint32_t)__cvta_generic_to_shared(dst + row*VPAD + col);
            asm volatile("cp.async.cg.shared.global [%0], [%1], 16;"
                         :: "r"(da), "l"(src + row*DD + col));
        }
        asm volatile("cp.async.commit_group;");
    };
    load_tile(0, 0);

    // ---- A fragments: W2^T rows [u0, u0+16), all K=256, tf32-rounded, regs ----
    uint32_t Af[32][4];
    #pragma unroll
    for (int kk = 0; kk < 32; kk++) {
        const float* w = W2 + (kk*8 + t) * UU;     // row k = 8kk+t of W2[d][u]
        Af[kk][0] = tf32_rna(w[u0 + g]);
        Af[kk][1] = tf32_rna(w[u0 + 8 + g]);
        Af[kk][2] = tf32_rna(w[4*UU + u0 + g]);    // row k = 8kk+t+4
        Af[kk][3] = tf32_rna(w[4*UU + u0 + 8 + g]);
    }
    const float qbg = g_qb[b*UU + u0 + g], qb8 = g_qb[b*UU + u0 + 8 + g];
    const float wvg = Wv[u0 + g],          wv8 = Wv[u0 + 8 + g];

    float cacc = 0.f;     // running context for d = tid
    float sacc = 0.f;     // exp-sum partial (sj == 0 threads)

    for (int tile = 0; tile < NTILES; ++tile) {
        const int buf = tile & 1;
        asm volatile("cp.async.wait_group 0;");
        __syncthreads();
        if (tile + 1 < NTILES) load_tile(tile + 1, buf ^ 1);
        const float* va = valsb + buf*TILE*VPAD;

        // ---- 4 chunk-pairs of 16 seq rows: D[u][n] = W2^T @ values^T ----
        #pragma unroll 1
        for (int c = 0; c < 4; c++) {
            const int n0 = c * 16;
            // 4 independent chains: [chunk(2)][khalf(2)], 4 accs each
            float acc[2][2][4];
            #pragma unroll
            for (int i = 0; i < 2; i++)
                #pragma unroll
                for (int j = 0; j < 2; j++)
                    #pragma unroll
                    for (int k = 0; k < 4; k++) acc[i][j][k] = 0.f;

            const float* brA = va + (n0 + g) * VPAD;       // seq rows n0..n0+7
            const float* brB = brA + 8 * VPAD;             // seq rows n0+8..n0+15
            #pragma unroll
            for (int kk = 0; kk < 16; kk++) {
                uint32_t bA0  = tf32_rna(brA[kk*8 + t]);
                uint32_t bA1  = tf32_rna(brA[kk*8 + t + 4]);
                uint32_t bB0  = tf32_rna(brB[kk*8 + t]);
                uint32_t bB1  = tf32_rna(brB[kk*8 + t + 4]);
                uint32_t bA0h = tf32_rna(brA[(kk+16)*8 + t]);
                uint32_t bA1h = tf32_rna(brA[(kk+16)*8 + t + 4]);
                uint32_t bB0h = tf32_rna(brB[(kk+16)*8 + t]);
                uint32_t bB1h = tf32_rna(brB[(kk+16)*8 + t + 4]);
                MMA4(acc[0][0][0], acc[0][0][1], acc[0][0][2], acc[0][0][3], Af[kk],    bA0,  bA1);
                MMA4(acc[1][0][0], acc[1][0][1], acc[1][0][2], acc[1][0][3], Af[kk],    bB0,  bB1);
                MMA4(acc[0][1][0], acc[0][1][1], acc[0][1][2], acc[0][1][3], Af[kk+16], bA0h, bA1h);
                MMA4(acc[1][1][0], acc[1][1][1], acc[1][1][2], acc[1][1][3], Af[kk+16], bB0h, bB1h);
            }

            // combine K-halves, epilogue per chunk: MUFU tanh -> *Wv -> reduce
            #pragma unroll
            for (int ch = 0; ch < 2; ch++) {
                float a0 = acc[ch][0][0] + acc[ch][1][0];
                float a1 = acc[ch][0][1] + acc[ch][1][1];
                float a2 = acc[ch][0][2] + acc[ch][1][2];
                float a3 = acc[ch][0][3] + acc[ch][1][3];
                float e0 = fast_tanh(a0 + qbg) * wvg;   // units u0+g,   col n0+8ch+2t
                float e1 = fast_tanh(a1 + qbg) * wvg;   //               col n0+8ch+2t+1
                float e2 = fast_tanh(a2 + qb8) * wv8;   // units u0+8+g, col n0+8ch+2t
                float e3 = fast_tanh(a3 + qb8) * wv8;
                float sc0 = e0 + e2, sc1 = e1 + e3;
                #pragma unroll
                for (int o = 4; o <= 16; o <<= 1) {
                    sc0 += __shfl_xor_sync(0xffffffffu, sc0, o);
                    sc1 += __shfl_xor_sync(0xffffffffu, sc1, o);
                }
                if (lane < 4) {
                    spart[wid*64 + n0 + 8*ch + 2*lane    ] = sc0;
                    spart[wid*64 + n0 + 8*ch + 2*lane + 1] = sc1;
                }
            }
        }
        __syncthreads();

        // ---- score reduce + exp across ALL threads: 4 threads per column ----
        {
            float sc = spart[(2*sj)*64 + scol] + spart[(2*sj + 1)*64 + scol];
            sc += __shfl_xor_sync(0xffffffffu, sc, 1);
            sc += __shfl_xor_sync(0xffffffffu, sc, 2);
            if (sj == 0) {
                float p = __expf(sc);
                sp[scol] = p;
                sacc += p;
                g_scores[(size_t)b*SS + s0 + tile*TILE + scol] = p;
            }
        }
        __syncthreads();

        // ---- context accumulate: ctx[d] += sum_r p[r] * vals[r][d] ----
        float csum = cacc;
        #pragma unroll 8
        for (int r = 0; r < TILE; ++r)
            csum += sp[r] * va[r*VPAD + tid];
        cacc = csum;
    }

    // ---- finalize exp-sum: every warp holds partials on lanes with sj==0 ----
    {
        float s = sacc;
        #pragma unroll
        for (int o = 16; o >= 1; o >>= 1) s += __shfl_xor_sync(0xffffffffu, s, o);
        if (lane == 0) sred[wid] = s;
    }
    __syncthreads();
    const int pi = b*SPLITS + split;
    if (tid == 0) {
        float s = 0.f;
        #pragma unroll
        for (int w = 0; w < 8; w++) s += sred[w];
        g_ps[pi] = s;
    }
    g_pctx[pi*DD + tid] = cacc;
}

// ---------------- kernel 3: merge split partials -> context ----------------
__global__ void merge_kernel(float* __restrict__ out_ctx) {
    int b = blockIdx.x, tid = threadIdx.x;    // 256 threads
    __shared__ float sinv;
    if (tid == 0) {
        float s = 0.f;
        #pragma unroll
        for (int i = 0; i < SPLITS; i++) s += g_ps[b*SPLITS + i];
        float inv = 1.f / s;
        sinv = inv;
        g_inv[b] = inv;
    }
    __syncthreads();
    float c = 0.f;
    #pragma unroll
    for (int i = 0; i < SPLITS; i++) c += g_pctx[(b*SPLITS + i)*DD + tid];
    out_ctx[b*DD + tid] = c * sinv;
}

// ---------------- kernel 4: normalized attention weights ----------------
__global__ void weights_kernel(float* __restrict__ out_w) {
    int i = blockIdx.x * blockDim.x + threadIdx.x;  // B*S total
    int b = i >> 12;
    out_w[i] = g_scores[i] * g_inv[b];
}

extern "C" void kernel_launch(void* const* d_in, const int* in_sizes, int n_in,
                              void* d_out, int out_size) {
    const float* query  = (const float*)d_in[0];
    const float* values = (const float*)d_in[1];
    const float* W1     = (const float*)d_in[2];
    const float* b1     = (const float*)d_in[3];
    const float* W2     = (const float*)d_in[4];
    const float* b2     = (const float*)d_in[5];
    const float* Wv     = (const float*)d_in[6];
    // d_in[7] = bv: constant over seq -> cancels in softmax.
    float* out = (float*)d_out;

    qproj_kernel<<<BB, UU>>>(query, W1, b1, b2);

    size_t smem_bytes = (size_t)(2*TILE*VPAD + 8*64 + 64 + 8) * sizeof(float);
    cudaFuncSetAttribute(attn_main, cudaFuncAttributeMaxDynamicSharedMemorySize, (int)smem_bytes);
    attn_main<<<dim3(SPLITS, BB), 256, smem_bytes>>>(values, W2, Wv);

    merge_kernel<<<BB, DD>>>(out);                       // context -> out[0 : 32768)
    weights_kernel<<<(BB*SS)/256, 256>>>(out + BB*DD);   // weights -> out[32768 : )
}